// round 5
// baseline (speedup 1.0000x reference)
#include <cuda_runtime.h>

#define T_STEPS 1024
#define WIN 64                       // live window: weights < 1e-12 earlier
#define WIN_PAIRS (WIN / 2)          // 32
#define T_HEAD (T_STEPS - WIN)       // 960
#define NBLK 128
#define NTHR 512

typedef unsigned long long u64;

__device__ __forceinline__ u64 pk2(float lo, float hi) {
    u64 r; asm("mov.b64 %0, {%1, %2};" : "=l"(r) : "f"(lo), "f"(hi)); return r;
}
__device__ __forceinline__ void up2(u64 v, float& lo, float& hi) {
    asm("mov.b64 {%0, %1}, %2;" : "=f"(lo), "=f"(hi) : "l"(v));
}
__device__ __forceinline__ u64 add2_(u64 a, u64 b) {
    u64 d; asm("add.rn.f32x2 %0, %1, %2;" : "=l"(d) : "l"(a), "l"(b)); return d;
}
__device__ __forceinline__ u64 fma2_(u64 a, u64 b, u64 c) {
    u64 d; asm("fma.rn.f32x2 %0, %1, %2, %3;" : "=l"(d) : "l"(a), "l"(b), "l"(c)); return d;
}

// One packed Riccati step. Pr[i][c] = (P[i][2c], P[i][2c+1]). Emits NEGATED
// Kalman gain kn (Sinv signs flipped) so the P update needs no negations:
// P_new[i][c] = Pp[i][c] + kn[i0]*Pp[0][c] + kn[i1]*Pp[1][c].
__device__ __forceinline__ void packed_step(u64 Pr[4][2], const u64 Q2[4][2],
                                            float R0f, float R1f, float R2f, float R3f,
                                            float kn[8]) {
    u64 U0 = add2_(Pr[0][0], Pr[0][1]);
    u64 U1 = add2_(Pr[1][0], Pr[1][1]);
    u64 U2 = add2_(Pr[2][0], Pr[2][1]);
    u64 U3 = add2_(Pr[3][0], Pr[3][1]);
    u64 Pp[4][2];
    Pp[0][0] = add2_(add2_(U0, U2), Q2[0][0]);
    Pp[0][1] = add2_(add2_(Pr[0][1], Pr[2][1]), Q2[0][1]);
    Pp[1][0] = add2_(add2_(U1, U3), Q2[1][0]);
    Pp[1][1] = add2_(add2_(Pr[1][1], Pr[3][1]), Q2[1][1]);
    Pp[2][0] = add2_(U2, Q2[2][0]);
    Pp[2][1] = add2_(Pr[2][1], Q2[2][1]);
    Pp[3][0] = add2_(U3, Q2[3][0]);
    Pp[3][1] = add2_(Pr[3][1], Q2[3][1]);

    float pp00, pp01, pp10, pp11, pp20, pp21, pp30, pp31;
    up2(Pp[0][0], pp00, pp01); up2(Pp[1][0], pp10, pp11);
    up2(Pp[2][0], pp20, pp21); up2(Pp[3][0], pp30, pp31);

    float s00 = pp00 + R0f, s01 = pp01 + R1f;
    float s10 = pp10 + R2f, s11 = pp11 + R3f;
    float id = __fdividef(1.0f, fmaf(s00, s11, -s01 * s10));
    float j00 = -s11 * id, j01 = s01 * id, j10 = s10 * id, j11 = -s00 * id;

    kn[0] = fmaf(pp00, j00, pp01 * j10); kn[1] = fmaf(pp00, j01, pp01 * j11);
    kn[2] = fmaf(pp10, j00, pp11 * j10); kn[3] = fmaf(pp10, j01, pp11 * j11);
    kn[4] = fmaf(pp20, j00, pp21 * j10); kn[5] = fmaf(pp20, j01, pp21 * j11);
    kn[6] = fmaf(pp30, j00, pp31 * j10); kn[7] = fmaf(pp30, j01, pp31 * j11);

    u64 b00 = pk2(kn[0], kn[0]), b01 = pk2(kn[1], kn[1]);
    u64 b10 = pk2(kn[2], kn[2]), b11 = pk2(kn[3], kn[3]);
    u64 b20 = pk2(kn[4], kn[4]), b21 = pk2(kn[5], kn[5]);
    u64 b30 = pk2(kn[6], kn[6]), b31 = pk2(kn[7], kn[7]);
#pragma unroll
    for (int c = 0; c < 2; c++) {
        Pr[0][c] = fma2_(b01, Pp[1][c], fma2_(b00, Pp[0][c], Pp[0][c]));
        Pr[1][c] = fma2_(b11, Pp[1][c], fma2_(b10, Pp[0][c], Pp[1][c]));
        Pr[2][c] = fma2_(b21, Pp[1][c], fma2_(b20, Pp[0][c], Pp[2][c]));
        Pr[3][c] = fma2_(b31, Pp[1][c], fma2_(b30, Pp[0][c], Pp[3][c]));
    }
}

// Single fused kernel. 128 blocks x 512 threads (1 block/SM); warp handles
// 2 sequences. z prefetch at kernel top hides DRAM under the per-block
// redundant serial Riccati (packed f32x2, ~95 instr/iter). Squarings done by
// 16-lane shuffle matmuls; W_n = Ainf^n Kinf by 64 threads.
__global__ void __launch_bounds__(NTHR) kf_fused(const float* __restrict__ hist,
                                                 const float* __restrict__ Qlog,
                                                 const float* __restrict__ Rlog,
                                                 float* __restrict__ out) {
    __shared__ float sW[WIN_PAIRS * 17];   // pair layout + pad
    __shared__ float sQR[20];              // exp(Qlog) (16) + exp(Rlog) (4)
    __shared__ float sApow[6][16];         // Ainf^(2^k)
    __shared__ float sKinf[8];
    __shared__ int   s_mode;               // 0 = converged, 1 = exact fallback
    __shared__ float sAwin[WIN * 16];      // fallback scratch
    __shared__ float sKwin[WIN * 8];

    int tid = threadIdx.x, warp = tid >> 5, lane = tid & 31;
    int bA = (blockIdx.x * 16 + warp) * 2;
    int bB = bA + 1;
    const float4* rowA = reinterpret_cast<const float4*>(hist) + (size_t)bA * 512;
    const float4* rowB = reinterpret_cast<const float4*>(hist) + (size_t)bB * 512;

    // Prefetch window pairs [480, 512) — in flight during the serial section.
    float4 zA = rowA[480 + lane];
    float4 zB = rowB[480 + lane];

    if (warp == 0) {
        // Parallel prologue: 20 lanes do loads + expf concurrently.
        if (lane < 20) {
            float v = (lane < 16) ? expf(Qlog[lane]) : expf(Rlog[lane - 16]);
            if (lane == 0 || lane == 5 || lane == 10 || lane == 15 ||
                lane == 16 || lane == 19)
                v += 1e-6f;
            sQR[lane] = v;
        }
        __syncwarp();

        if (lane == 0) {
            u64 Q2[4][2];
#pragma unroll
            for (int i = 0; i < 4; i++) {
                Q2[i][0] = pk2(sQR[i * 4 + 0], sQR[i * 4 + 1]);
                Q2[i][1] = pk2(sQR[i * 4 + 2], sQR[i * 4 + 3]);
            }
            float R0f = sQR[16], R1f = sQR[17], R2f = sQR[18], R3f = sQR[19];

            u64 Pr[4][2];
            Pr[0][0] = pk2(1000.f, 0.f);  Pr[0][1] = pk2(0.f, 0.f);
            Pr[1][0] = pk2(0.f, 1000.f);  Pr[1][1] = pk2(0.f, 0.f);
            Pr[2][0] = pk2(0.f, 0.f);     Pr[2][1] = pk2(1000.f, 0.f);
            Pr[3][0] = pk2(0.f, 0.f);     Pr[3][1] = pk2(0.f, 1000.f);

            float kn[8];
            float p0 = 1e30f, p1 = 1e30f, p2 = 1e30f, p3 = 1e30f;
            int mode = 1, stable = 0;

            for (int t = 0; t < T_HEAD; t++) {
                packed_step(Pr, Q2, R0f, R1f, R2f, R3f, kn);
                if (t >= 12) {
                    float d = fabsf(kn[0] - p0);
                    d = fmaxf(d, fabsf(kn[3] - p1));
                    d = fmaxf(d, fabsf(kn[4] - p2));
                    d = fmaxf(d, fabsf(kn[7] - p3));
                    float km = fmaxf(fmaxf(fabsf(kn[0]), fabsf(kn[3])),
                                     fmaxf(fabsf(kn[4]), fabsf(kn[7])));
                    if (d <= 1e-5f * km) {
                        if (++stable >= 3) { mode = 0; }
                    } else {
                        stable = 0;
                    }
                    if (mode == 0) break;
                }
                p0 = kn[0]; p1 = kn[3]; p2 = kn[4]; p3 = kn[7];
            }

            if (mode == 0) {
                // K = -kn; A = (I - K H) F; stash for squarings + W build.
#pragma unroll
                for (int i = 0; i < 4; i++) {
                    float a0 = (i == 0 ? 1.0f : 0.0f) + kn[i * 2 + 0];
                    float a1 = (i == 1 ? 1.0f : 0.0f) + kn[i * 2 + 1];
                    sApow[0][i * 4 + 0] = a0;
                    sApow[0][i * 4 + 1] = a1;
                    sApow[0][i * 4 + 2] = a0 + (i == 2 ? 1.0f : 0.0f);
                    sApow[0][i * 4 + 3] = a1 + (i == 3 ? 1.0f : 0.0f);
                }
#pragma unroll
                for (int q = 0; q < 8; q++) sKinf[q] = -kn[q];
            } else {
                // No early convergence: exact steps through the window.
                for (int tw = 0; tw < WIN; tw++) {
                    packed_step(Pr, Q2, R0f, R1f, R2f, R3f, kn);
#pragma unroll
                    for (int i = 0; i < 4; i++) {
                        float a0 = (i == 0 ? 1.0f : 0.0f) + kn[i * 2 + 0];
                        float a1 = (i == 1 ? 1.0f : 0.0f) + kn[i * 2 + 1];
                        sAwin[tw * 16 + i * 4 + 0] = a0;
                        sAwin[tw * 16 + i * 4 + 1] = a1;
                        sAwin[tw * 16 + i * 4 + 2] = a0 + (i == 2 ? 1.0f : 0.0f);
                        sAwin[tw * 16 + i * 4 + 3] = a1 + (i == 3 ? 1.0f : 0.0f);
                    }
#pragma unroll
                    for (int q = 0; q < 8; q++) sKwin[tw * 8 + q] = -kn[q];
                }
            }
            s_mode = mode;
        }
        __syncwarp();

        if (s_mode == 0) {
            // Shuffle squarings: lane (i*4+j) owns element (i,j). Lanes 16-31
            // mirror lanes 0-15 (harmless duplicates keep shuffles valid).
            int i4 = (lane >> 2) & 3, j4 = lane & 3;
            float a = sApow[0][lane & 15];
#pragma unroll
            for (int k = 1; k < 6; k++) {
                float c = 0.0f;
#pragma unroll
                for (int m = 0; m < 4; m++) {
                    float rim = __shfl_sync(0xffffffffu, a, i4 * 4 + m);
                    float rmj = __shfl_sync(0xffffffffu, a, m * 4 + j4);
                    c = fmaf(rim, rmj, c);
                }
                a = c;
                if (lane < 16) sApow[k][lane] = a;
            }
        } else if (lane == 0) {
            // Exact backward suffix within the window.
            float S[16];
#pragma unroll
            for (int q = 0; q < 16; q++) S[q] = (q % 5 == 0) ? 1.0f : 0.0f;
            for (int tw = WIN - 1; tw >= 0; tw--) {
                const float* K = &sKwin[tw * 8];
                float V[8];
#pragma unroll
                for (int i = 0; i < 4; i++) {
#pragma unroll
                    for (int c = 0; c < 2; c++) {
                        float s = S[i * 4 + 0] * K[0 * 2 + c];
                        s = fmaf(S[i * 4 + 1], K[1 * 2 + c], s);
                        s = fmaf(S[i * 4 + 2], K[2 * 2 + c], s);
                        s = fmaf(S[i * 4 + 3], K[3 * 2 + c], s);
                        V[i * 2 + c] = s;
                    }
                }
                int pw = tw >> 1, sub = tw & 1;   // (T_HEAD+tw)&1 == tw&1
#pragma unroll
                for (int q = 0; q < 8; q++) sW[pw * 17 + sub * 8 + q] = V[q];
                const float* Aw = &sAwin[tw * 16];
                float Sn[16];
#pragma unroll
                for (int i = 0; i < 4; i++) {
#pragma unroll
                    for (int c = 0; c < 4; c++) {
                        float s = S[i * 4 + 0] * Aw[0 * 4 + c];
                        s = fmaf(S[i * 4 + 1], Aw[1 * 4 + c], s);
                        s = fmaf(S[i * 4 + 2], Aw[2 * 4 + c], s);
                        s = fmaf(S[i * 4 + 3], Aw[3 * 4 + c], s);
                        Sn[i * 4 + c] = s;
                    }
                }
#pragma unroll
                for (int q = 0; q < 16; q++) S[q] = Sn[q];
            }
        }
    }
    __syncthreads();

    // Fast path: thread n builds W_{T-1-n} = Ainf^n Kinf (n = 0..63).
    if (s_mode == 0 && tid < WIN) {
        int n = tid;
        float V[8];
#pragma unroll
        for (int q = 0; q < 8; q++) V[q] = sKinf[q];
#pragma unroll
        for (int k = 0; k < 6; k++) {
            if ((n >> k) & 1) {
                const float* M = sApow[k];
                float Vn[8];
#pragma unroll
                for (int i = 0; i < 4; i++) {
#pragma unroll
                    for (int c = 0; c < 2; c++) {
                        float s = M[i * 4 + 0] * V[0 * 2 + c];
                        s = fmaf(M[i * 4 + 1], V[1 * 2 + c], s);
                        s = fmaf(M[i * 4 + 2], V[2 * 2 + c], s);
                        s = fmaf(M[i * 4 + 3], V[3 * 2 + c], s);
                        Vn[i * 2 + c] = s;
                    }
                }
#pragma unroll
                for (int q = 0; q < 8; q++) V[q] = Vn[q];
            }
        }
        int tw = WIN - 1 - n;
        int pw = tw >> 1, sub = tw & 1;
#pragma unroll
        for (int q = 0; q < 8; q++) sW[pw * 17 + sub * 8 + q] = V[q];
    }
    __syncthreads();

    // Weighted sum: lane handles pair (T_HEAD + 2*lane, +1) for 2 sequences.
    float a0 = 0.f, a1 = 0.f, a2 = 0.f, a3 = 0.f;
    float c0 = 0.f, c1 = 0.f, c2 = 0.f, c3 = 0.f;
    const float* w = &sW[lane * 17];

    a0 = fmaf(w[0],  zA.x, a0); a0 = fmaf(w[1],  zA.y, a0);
    a1 = fmaf(w[2],  zA.x, a1); a1 = fmaf(w[3],  zA.y, a1);
    a2 = fmaf(w[4],  zA.x, a2); a2 = fmaf(w[5],  zA.y, a2);
    a3 = fmaf(w[6],  zA.x, a3); a3 = fmaf(w[7],  zA.y, a3);
    a0 = fmaf(w[8],  zA.z, a0); a0 = fmaf(w[9],  zA.w, a0);
    a1 = fmaf(w[10], zA.z, a1); a1 = fmaf(w[11], zA.w, a1);
    a2 = fmaf(w[12], zA.z, a2); a2 = fmaf(w[13], zA.w, a2);
    a3 = fmaf(w[14], zA.z, a3); a3 = fmaf(w[15], zA.w, a3);

    c0 = fmaf(w[0],  zB.x, c0); c0 = fmaf(w[1],  zB.y, c0);
    c1 = fmaf(w[2],  zB.x, c1); c1 = fmaf(w[3],  zB.y, c1);
    c2 = fmaf(w[4],  zB.x, c2); c2 = fmaf(w[5],  zB.y, c2);
    c3 = fmaf(w[6],  zB.x, c3); c3 = fmaf(w[7],  zB.y, c3);
    c0 = fmaf(w[8],  zB.z, c0); c0 = fmaf(w[9],  zB.w, c0);
    c1 = fmaf(w[10], zB.z, c1); c1 = fmaf(w[11], zB.w, c1);
    c2 = fmaf(w[12], zB.z, c2); c2 = fmaf(w[13], zB.w, c2);
    c3 = fmaf(w[14], zB.z, c3); c3 = fmaf(w[15], zB.w, c3);

#pragma unroll
    for (int s = 16; s > 0; s >>= 1) {
        a0 += __shfl_xor_sync(0xffffffffu, a0, s);
        a1 += __shfl_xor_sync(0xffffffffu, a1, s);
        a2 += __shfl_xor_sync(0xffffffffu, a2, s);
        a3 += __shfl_xor_sync(0xffffffffu, a3, s);
        c0 += __shfl_xor_sync(0xffffffffu, c0, s);
        c1 += __shfl_xor_sync(0xffffffffu, c1, s);
        c2 += __shfl_xor_sync(0xffffffffu, c2, s);
        c3 += __shfl_xor_sync(0xffffffffu, c3, s);
    }

    if (lane == 0) {
        float* oA = out + (size_t)bA * 6;
        oA[0] = a0 + a2;            oA[1] = a1 + a3;
        oA[2] = fmaf(2.f, a2, a0);  oA[3] = fmaf(2.f, a3, a1);
        oA[4] = fmaf(3.f, a2, a0);  oA[5] = fmaf(3.f, a3, a1);
        float* oB = out + (size_t)bB * 6;
        oB[0] = c0 + c2;            oB[1] = c1 + c3;
        oB[2] = fmaf(2.f, c2, c0);  oB[3] = fmaf(2.f, c3, c1);
        oB[4] = fmaf(3.f, c2, c0);  oB[5] = fmaf(3.f, c3, c1);
    }
}

extern "C" void kernel_launch(void* const* d_in, const int* in_sizes, int n_in,
                              void* d_out, int out_size) {
    const float* hist = (const float*)d_in[0];
    const float* Qlog = (const float*)d_in[1];
    const float* Rlog = (const float*)d_in[2];
    float* out = (float*)d_out;

    kf_fused<<<NBLK, NTHR>>>(hist, Qlog, Rlog, out);
}